// round 10
// baseline (speedup 1.0000x reference)
#include <cuda_runtime.h>

typedef unsigned long long u64;

// ---------------- f32x2 packed-math helpers (sm_103a) ----------------
__device__ __forceinline__ u64 f2fma(u64 a, u64 b, u64 c) {
    u64 d;
    asm("fma.rn.f32x2 %0, %1, %2, %3;" : "=l"(d) : "l"(a), "l"(b), "l"(c));
    return d;
}
__device__ __forceinline__ u64 f2mul(u64 a, u64 b) {
    u64 d;
    asm("mul.rn.f32x2 %0, %1, %2;" : "=l"(d) : "l"(a), "l"(b));
    return d;
}
__device__ __forceinline__ u64 f2add(u64 a, u64 b) {
    u64 d;
    asm("add.rn.f32x2 %0, %1, %2;" : "=l"(d) : "l"(a), "l"(b));
    return d;
}
__device__ __forceinline__ u64 fpack(float x, float y) {
    u64 d;
    asm("mov.b64 %0, {%1, %2};" : "=l"(d) : "f"(x), "f"(y));
    return d;
}
__device__ __forceinline__ float2 funpack(u64 a) {
    float2 r;
    asm("mov.b64 {%0, %1}, %2;" : "=f"(r.x), "=f"(r.y) : "l"(a));
    return r;
}

// ---------------- problem constants ----------------
#define NN     50000
#define KC     128
#define PC     256
#define BN     8
#define NT     512
#define NI     4
#define EPSV   1e-6f

// smem layout (float offsets)
#define OFF_RES 0          // [8][9][128]  residual                 9216
#define OFF_H   9216       // [8][9][128]  normed h / lin_out scratch 9216
#define OFF_HC  18432      // [8][9][256]  hc / tp                  18432
#define OFF_U   36864      // [45][9] scalar sym U                  405
#define OFF_G   37312      // [4][3][128]  gamma                    1536
#define SMEM_FLOATS 38848

// ---------------- linear_in: RB rows x 8 interleaved p-cols, k-half ----------------
// roff[j]: row offsets in s_h units (row*128). Output cols p = pg*2 + 64u (+0/1).
template<int RB>
__device__ __forceinline__ void li_body(const float* __restrict__ W,
        const float* __restrict__ s_h, float* __restrict__ s_hc,
        const int* roff, int pg, int ks, u64 (*acc)[4])
{
    #pragma unroll
    for (int j = 0; j < RB; j++)
        #pragma unroll
        for (int u = 0; u < 4; u++) acc[j][u] = 0ull;

    const int k0 = ks * 64;
    const float* Wb = W + (size_t)k0 * PC + pg * 2;

    #pragma unroll 2
    for (int kk = 0; kk < 64; kk += 2) {
        const float* wk = Wb + (size_t)kk * PC;
        u64 w0[4], w1[4];
        #pragma unroll
        for (int u = 0; u < 4; u++) {
            w0[u] = *(const u64*)(wk + 64 * u);
            w1[u] = *(const u64*)(wk + PC + 64 * u);
        }
        #pragma unroll
        for (int j = 0; j < RB; j++) {
            const float2 hp = *(const float2*)(s_h + roff[j] + k0 + kk);
            u64 ha = fpack(hp.x, hp.x);
            u64 hb = fpack(hp.y, hp.y);
            #pragma unroll
            for (int u = 0; u < 4; u++) {
                acc[j][u] = f2fma(ha, w0[u], acc[j][u]);
                acc[j][u] = f2fma(hb, w1[u], acc[j][u]);
            }
        }
    }
    if (ks == 1) {
        #pragma unroll
        for (int j = 0; j < RB; j++)
            #pragma unroll
            for (int u = 0; u < 4; u++)
                *(u64*)(s_hc + roff[j] * 2 + pg * 2 + 64 * u) = acc[j][u];
    }
}

template<int RB>
__device__ __forceinline__ void li_fin(float* __restrict__ s_hc,
        const int* roff, int pg, u64 (*acc)[4])
{
    #pragma unroll
    for (int j = 0; j < RB; j++)
        #pragma unroll
        for (int u = 0; u < 4; u++) {
            float* dst = s_hc + roff[j] * 2 + pg * 2 + 64 * u;
            *(u64*)dst = f2add(acc[j][u], *(const u64*)dst);
        }
}

// ---------------- linear_out: RB rows x 8 interleaved c-cols, p-half ----------------
// rhc[j]: row offsets in s_hc units (row*256). Output cols c = cg*2 + 32u (+0/1).
template<int RB>
__device__ __forceinline__ void lo_body(const float* __restrict__ W,
        const float* __restrict__ s_hc, float* __restrict__ scr,
        const int* rhc, int cg, int ps, u64 (*acc)[4])
{
    #pragma unroll
    for (int j = 0; j < RB; j++)
        #pragma unroll
        for (int u = 0; u < 4; u++) acc[j][u] = 0ull;

    const int p0 = ps * 128;
    const float* Wb = W + (size_t)p0 * KC + cg * 2;

    #pragma unroll 2
    for (int pp = 0; pp < 128; pp += 2) {
        const float* wk = Wb + (size_t)pp * KC;
        u64 w0[4], w1[4];
        #pragma unroll
        for (int u = 0; u < 4; u++) {
            w0[u] = *(const u64*)(wk + 32 * u);
            w1[u] = *(const u64*)(wk + KC + 32 * u);
        }
        #pragma unroll
        for (int j = 0; j < RB; j++) {
            const float2 t = *(const float2*)(s_hc + rhc[j] + p0 + pp);
            u64 ta = fpack(t.x, t.x);
            u64 tb = fpack(t.y, t.y);
            #pragma unroll
            for (int u = 0; u < 4; u++) {
                acc[j][u] = f2fma(ta, w0[u], acc[j][u]);
                acc[j][u] = f2fma(tb, w1[u], acc[j][u]);
            }
        }
    }
    if (ps == 1) {
        #pragma unroll
        for (int j = 0; j < RB; j++)
            #pragma unroll
            for (int u = 0; u < 4; u++)
                *(u64*)(scr + (j * 4 + u) * 32 + cg * 2) = acc[j][u];
    }
}

template<int RB>
__device__ __forceinline__ void lo_fin(float* __restrict__ s_res,
        const float* __restrict__ scr, const int* rhc, int cg, u64 (*acc)[4])
{
    #pragma unroll
    for (int j = 0; j < RB; j++)
        #pragma unroll
        for (int u = 0; u < 4; u++) {
            u64 part = *(const u64*)(scr + (j * 4 + u) * 32 + cg * 2);
            float* dst = s_res + (rhc[j] >> 1) + cg * 2 + 32 * u;
            *(u64*)dst = f2add(*(const u64*)dst, f2add(acc[j][u], part));
        }
}

// ---------------- fused 4-iteration kernel, 8 nodes per CTA, 512 threads ----------------
__global__ void __launch_bounds__(NT, 1)
cg_kernel(const float* __restrict__ f0, const float* __restrict__ f1,
          const float* __restrict__ f2, const float* __restrict__ U,
          const float* __restrict__ gamma, const float* __restrict__ Win,
          const float* __restrict__ Wout, float* __restrict__ out)
{
    extern __shared__ float sm[];
    float* s_res = sm + OFF_RES;
    float* s_h   = sm + OFF_H;
    float* s_hc  = sm + OFF_HC;
    float* s_U   = sm + OFF_U;
    float* s_g   = sm + OFF_G;

    const int tid = threadIdx.x;
    const int n0  = blockIdx.x * BN;

    // ----- lin_in task mapping (computed once) -----
    int li_roff[10];
    int li_pg, li_ks, li_l;
    if (tid < 256) {            // l=2: 4 bmg x 32 pg x 2 ks (warps 0-7)
        li_l = 2; li_pg = tid & 31;
        int bmg = (tid >> 5) & 3; li_ks = tid >> 7;
        #pragma unroll
        for (int j = 0; j < 10; j++) {
            int idx = bmg * 10 + j;
            int b = idx / 5, q = idx - b * 5;
            li_roff[j] = (b * 9 + 4 + q) * 128;
        }
    } else if (tid < 448) {     // l=1: 3 bmg x 32 pg x 2 ks (warps 8-13)
        li_l = 1; int t = tid - 256; li_pg = t & 31;
        int g = t >> 5; int bmg = g % 3; li_ks = g / 3;
        #pragma unroll
        for (int j = 0; j < 8; j++) {
            int idx = bmg * 8 + j;
            int b = idx / 3, q = idx - b * 3;
            li_roff[j] = (b * 9 + 1 + q) * 128;
        }
        li_roff[8] = li_roff[9] = 0;
    } else {                    // l=0: 1 x 32 pg x 2 ks (warps 14-15)
        li_l = 0; int t = tid - 448; li_pg = t & 31; li_ks = t >> 5;
        #pragma unroll
        for (int j = 0; j < 8; j++) li_roff[j] = j * 9 * 128;
        li_roff[8] = li_roff[9] = 0;
    }

    // ----- lin_out task mapping (256 active threads) -----
    int lo_roff[10];
    int lo_cg = 0, lo_ps = 0, lo_l = 0;
    float* lo_scr = s_h;
    const bool lo_act = tid < 256;
    if (tid < 128) {            // l=2: 4 bmg x 16 cg x 2 ps (warps 0-3)
        lo_l = 2; lo_cg = tid & 15;
        int bmg = (tid >> 4) & 3; lo_ps = tid >> 6;
        lo_scr = s_h + 4096 + bmg * 1280;
        #pragma unroll
        for (int j = 0; j < 10; j++) {
            int idx = bmg * 10 + j;
            int b = idx / 5, q = idx - b * 5;
            lo_roff[j] = (b * 9 + 4 + q) * 256;
        }
    } else if (tid < 224) {     // l=1: 3 bmg x 16 cg x 2 ps (warps 4-6)
        lo_l = 1; int t = tid - 128; lo_cg = t & 15;
        int g = t >> 4; int bmg = g % 3; lo_ps = g / 3;
        lo_scr = s_h + 1024 + bmg * 1024;
        #pragma unroll
        for (int j = 0; j < 8; j++) {
            int idx = bmg * 8 + j;
            int b = idx / 3, q = idx - b * 3;
            lo_roff[j] = (b * 9 + 1 + q) * 256;
        }
        lo_roff[8] = lo_roff[9] = 0;
    } else if (tid < 256) {     // l=0: 1 x 16 cg x 2 ps (warp 7)
        lo_l = 0; int t = tid - 224; lo_cg = t & 15; lo_ps = t >> 4;
        lo_scr = s_h;
        #pragma unroll
        for (int j = 0; j < 8; j++) lo_roff[j] = j * 9 * 256;
        lo_roff[8] = lo_roff[9] = 0;
    } else {
        #pragma unroll
        for (int j = 0; j < 10; j++) lo_roff[j] = 0;
    }

    // --- load features: s_res[b][m][k], m packed [f0 | f1(3) | f2(5)] ---
    {
        float4* dst = (float4*)s_res;
        for (int idx = tid; idx < BN * 9 * 32; idx += NT) {
            int b   = idx / 288;
            int rem = idx - b * 288;
            int m   = rem >> 5;
            int q   = rem & 31;
            int n   = n0 + b;
            const float* src;
            if (m == 0)      src = f0 + (size_t)n * 128;
            else if (m < 4)  src = f1 + (size_t)n * 384 + (m - 1) * 128;
            else             src = f2 + (size_t)n * 640 + (m - 4) * 128;
            dst[idx] = ((const float4*)src)[q];
        }
    }
    // --- symmetrize U into scalar pair layout s_U[pair][c] ---
    for (int tt = tid; tt < 45 * 9; tt += NT) {
        int pair = tt / 9, c = tt - pair * 9;
        int a = 0, rem = pair;
        while (rem > 8 - a) { rem -= 9 - a; a++; }
        int bb = a + rem;
        float u = U[(a * 9 + bb) * 9 + c];
        if (a != bb) u += U[(bb * 9 + a) * 9 + c];
        s_U[pair * 9 + c] = u;
    }
    for (int tt = tid; tt < NI * 3 * KC; tt += NT) s_g[tt] = gamma[tt];
    __syncthreads();

    u64 acc[10][4];

    #pragma unroll 1
    for (int it = 0; it < NI; it++) {
        // ---------- EquivariantRMSNorm -> natural h[b][m][k] ----------
        for (int idx = tid; idx < BN * KC; idx += NT) {
            int b = idx >> 7, k = idx & 127;
            const float* r = s_res + b * 1152 + k;
            float x0 = r[0];
            float x1 = r[128], x2 = r[256],  x3 = r[384];
            float x4 = r[512], x5 = r[640],  x6 = r[768], x7 = r[896], x8 = r[1024];
            float i0 = rsqrtf(x0 * x0 + EPSV);
            float i1 = rsqrtf((x1*x1 + x2*x2 + x3*x3) * (1.0f/3.0f) + EPSV);
            float i2 = rsqrtf((x4*x4 + x5*x5 + x6*x6 + x7*x7 + x8*x8) * 0.2f + EPSV);
            float g0 = s_g[(it * 3 + 0) * 128 + k];
            float g1 = s_g[(it * 3 + 1) * 128 + k];
            float g2 = s_g[(it * 3 + 2) * 128 + k];
            float* h = s_h + b * 1152 + k;
            h[0]    = x0 * i0 * g0;
            h[128]  = x1 * i1 * g1;
            h[256]  = x2 * i1 * g1;
            h[384]  = x3 * i1 * g1;
            h[512]  = x4 * i2 * g2;
            h[640]  = x5 * i2 * g2;
            h[768]  = x6 * i2 * g2;
            h[896]  = x7 * i2 * g2;
            h[1024] = x8 * i2 * g2;
        }
        __syncthreads();

        // ---------- linear_in (K -> 2K): register-tiled, k-halves ----------
        {
            const float* Wl = Win + (size_t)(it * 3 + li_l) * KC * PC;
            if (tid < 256)       li_body<10>(Wl, s_h, s_hc, li_roff, li_pg, li_ks, acc);
            else if (tid < 448)  li_body<8>(Wl, s_h, s_hc, li_roff, li_pg, li_ks, acc);
            else                 li_body<8>(Wl, s_h, s_hc, li_roff, li_pg, li_ks, acc);
        }
        __syncthreads();
        if (li_ks == 0) {
            if (tid < 256)       li_fin<10>(s_hc, li_roff, li_pg, acc);
            else if (tid < 448)  li_fin<8>(s_hc, li_roff, li_pg, acc);
            else                 li_fin<8>(s_hc, li_roff, li_pg, acc);
        }
        __syncthreads();

        // ---------- CG tensor product, register-preloaded, in-place on s_hc ----------
        {
            const int p2 = tid & 127;
            const int bq = (tid >> 7) * 2;
            float* base0 = s_hc + bq * 2304 + 2 * p2;
            float* base1 = base0 + 2304;
            u64 v0[9], v1[9];
            #pragma unroll
            for (int a = 0; a < 9; a++) {
                v0[a] = *(const u64*)(base0 + a * 256);
                v1[a] = *(const u64*)(base1 + a * 256);
            }
            u64 acc0[9], acc1[9];
            #pragma unroll
            for (int c = 0; c < 9; c++) { acc0[c] = 0ull; acc1[c] = 0ull; }
            int pair = 0;
            for (int a = 0; a < 9; a++) {
                for (int bb = a; bb < 9; bb++) {
                    u64 pr0 = f2mul(v0[a], v0[bb]);
                    u64 pr1 = f2mul(v1[a], v1[bb]);
                    const float* u = s_U + pair * 9;
                    #pragma unroll
                    for (int c = 0; c < 9; c++) {
                        float us = u[c];
                        u64 uc = fpack(us, us);
                        acc0[c] = f2fma(pr0, uc, acc0[c]);
                        acc1[c] = f2fma(pr1, uc, acc1[c]);
                    }
                    pair++;
                }
            }
            #pragma unroll
            for (int c = 0; c < 9; c++) {
                *(u64*)(base0 + c * 256) = acc0[c];
                *(u64*)(base1 + c * 256) = acc1[c];
            }
        }
        __syncthreads();

        // ---------- linear_out (2K -> K) + skip: register-tiled, p-halves ----------
        {
            const float* Wl = Wout + (size_t)(it * 3 + lo_l) * PC * KC;
            if (lo_act) {
                if (tid < 128)       lo_body<10>(Wl, s_hc, lo_scr, lo_roff, lo_cg, lo_ps, acc);
                else if (tid < 224)  lo_body<8>(Wl, s_hc, lo_scr, lo_roff, lo_cg, lo_ps, acc);
                else                 lo_body<8>(Wl, s_hc, lo_scr, lo_roff, lo_cg, lo_ps, acc);
            }
        }
        __syncthreads();
        if (lo_act && lo_ps == 0) {
            if (tid < 128)       lo_fin<10>(s_res, lo_scr, lo_roff, lo_cg, acc);
            else if (tid < 224)  lo_fin<8>(s_res, lo_scr, lo_roff, lo_cg, acc);
            else                 lo_fin<8>(s_res, lo_scr, lo_roff, lo_cg, acc);
        }
        __syncthreads();
    }

    // --- write out [N][9][128] ---
    {
        float4* o = (float4*)(out + (size_t)n0 * 1152);
        const float4* s = (const float4*)s_res;
        for (int idx = tid; idx < BN * 9 * 32; idx += NT) o[idx] = s[idx];
    }
}

extern "C" void kernel_launch(void* const* d_in, const int* in_sizes, int n_in,
                              void* d_out, int out_size)
{
    const float* f0 = (const float*)d_in[0];
    const float* f1 = (const float*)d_in[1];
    const float* f2 = (const float*)d_in[2];
    const float* U  = (const float*)d_in[3];
    const float* g  = (const float*)d_in[4];
    const float* Wi = (const float*)d_in[5];
    const float* Wo = (const float*)d_in[6];
    float* out = (float*)d_out;

    const int smem_bytes = SMEM_FLOATS * (int)sizeof(float);
    cudaFuncSetAttribute(cg_kernel, cudaFuncAttributeMaxDynamicSharedMemorySize, smem_bytes);
    cg_kernel<<<NN / BN, NT, smem_bytes>>>(f0, f1, f2, U, g, Wi, Wo, out);
}

// round 11
// speedup vs baseline: 1.1911x; 1.1911x over previous
#include <cuda_runtime.h>

typedef unsigned long long u64;

// ---------------- f32x2 packed-math helpers (sm_103a) ----------------
__device__ __forceinline__ u64 f2fma(u64 a, u64 b, u64 c) {
    u64 d;
    asm("fma.rn.f32x2 %0, %1, %2, %3;" : "=l"(d) : "l"(a), "l"(b), "l"(c));
    return d;
}
__device__ __forceinline__ u64 f2mul(u64 a, u64 b) {
    u64 d;
    asm("mul.rn.f32x2 %0, %1, %2;" : "=l"(d) : "l"(a), "l"(b));
    return d;
}
__device__ __forceinline__ u64 f2add(u64 a, u64 b) {
    u64 d;
    asm("add.rn.f32x2 %0, %1, %2;" : "=l"(d) : "l"(a), "l"(b));
    return d;
}
__device__ __forceinline__ u64 fpack(float x, float y) {
    u64 d;
    asm("mov.b64 %0, {%1, %2};" : "=l"(d) : "f"(x), "f"(y));
    return d;
}
__device__ __forceinline__ float2 funpack(u64 a) {
    float2 r;
    asm("mov.b64 {%0, %1}, %2;" : "=f"(r.x), "=f"(r.y) : "l"(a));
    return r;
}

// ---------------- problem constants ----------------
#define NN     50000
#define KC     128
#define PC     256
#define BN     8
#define NT     512
#define NI     4
#define EPSV   1e-6f

// smem layout (float offsets)
#define OFF_RES 0          // [8][9][128]  residual                   9216
#define OFF_H   9216       // [8][9][128]  normed h / lin_out scratch 9216
#define OFF_HC  18432      // [8][9][256]  hc / tp                    18432
#define OFF_U   36864      // [45][9] scalar sym U                    405
#define OFF_G   37312      // [4][3][128]  gamma                      1536
#define SMEM_FLOATS 38848

// ---------------- linear_in: RB rows x 8 interleaved p-cols, k-half ----------------
// roff[j]: row offsets in s_h units (row*128). Output cols p = pg*2 + 64u (+0/1).
template<int RB>
__device__ __forceinline__ void li_body(const float* __restrict__ W,
        const float* __restrict__ s_h, float* __restrict__ s_hc,
        const int* roff, int pg, int ks, u64 (*acc)[4])
{
    #pragma unroll
    for (int j = 0; j < RB; j++)
        #pragma unroll
        for (int u = 0; u < 4; u++) acc[j][u] = 0ull;

    const int k0 = ks * 64;
    const float* Wb = W + (size_t)k0 * PC + pg * 2;

    #pragma unroll 2
    for (int kk = 0; kk < 64; kk += 2) {
        const float* wk = Wb + (size_t)kk * PC;
        u64 w0[4], w1[4];
        #pragma unroll
        for (int u = 0; u < 4; u++) {
            w0[u] = *(const u64*)(wk + 64 * u);
            w1[u] = *(const u64*)(wk + PC + 64 * u);
        }
        #pragma unroll
        for (int j = 0; j < RB; j++) {
            const float2 hp = *(const float2*)(s_h + roff[j] + k0 + kk);
            u64 ha = fpack(hp.x, hp.x);
            u64 hb = fpack(hp.y, hp.y);
            #pragma unroll
            for (int u = 0; u < 4; u++) {
                acc[j][u] = f2fma(ha, w0[u], acc[j][u]);
                acc[j][u] = f2fma(hb, w1[u], acc[j][u]);
            }
        }
    }
    if (ks == 1) {
        #pragma unroll
        for (int j = 0; j < RB; j++)
            #pragma unroll
            for (int u = 0; u < 4; u++)
                *(u64*)(s_hc + roff[j] * 2 + pg * 2 + 64 * u) = acc[j][u];
    }
}

template<int RB>
__device__ __forceinline__ void li_fin(float* __restrict__ s_hc,
        const int* roff, int pg, u64 (*acc)[4])
{
    #pragma unroll
    for (int j = 0; j < RB; j++)
        #pragma unroll
        for (int u = 0; u < 4; u++) {
            float* dst = s_hc + roff[j] * 2 + pg * 2 + 64 * u;
            *(u64*)dst = f2add(acc[j][u], *(const u64*)dst);
        }
}

// ---------------- linear_out: RB rows x 8 interleaved c-cols, p-half, 512 tasks ----------------
// rhc[j]: row offsets in s_hc units (row*256). scr: per-thread scratch base
// ([row][128] layout). Output cols c = cg*2 + 32u (+0/1).
template<int RB>
__device__ __forceinline__ void lo_body(const float* __restrict__ W,
        const float* __restrict__ s_hc, float* __restrict__ scr,
        const int* rhc, int cg, int ps, u64 (*acc)[4])
{
    #pragma unroll
    for (int j = 0; j < RB; j++)
        #pragma unroll
        for (int u = 0; u < 4; u++) acc[j][u] = 0ull;

    const int p0 = ps * 128;
    const float* Wb = W + (size_t)p0 * KC + cg * 2;

    #pragma unroll 2
    for (int pp = 0; pp < 128; pp += 2) {
        const float* wk = Wb + (size_t)pp * KC;
        u64 w0[4], w1[4];
        #pragma unroll
        for (int u = 0; u < 4; u++) {
            w0[u] = *(const u64*)(wk + 32 * u);
            w1[u] = *(const u64*)(wk + KC + 32 * u);
        }
        #pragma unroll
        for (int j = 0; j < RB; j++) {
            const float2 t = *(const float2*)(s_hc + rhc[j] + p0 + pp);
            u64 ta = fpack(t.x, t.x);
            u64 tb = fpack(t.y, t.y);
            #pragma unroll
            for (int u = 0; u < 4; u++) {
                acc[j][u] = f2fma(ta, w0[u], acc[j][u]);
                acc[j][u] = f2fma(tb, w1[u], acc[j][u]);
            }
        }
    }
    if (ps == 1) {
        #pragma unroll
        for (int j = 0; j < RB; j++)
            #pragma unroll
            for (int u = 0; u < 4; u++)
                *(u64*)(scr + j * 128 + 32 * u + cg * 2) = acc[j][u];
    }
}

template<int RB>
__device__ __forceinline__ void lo_fin(float* __restrict__ s_res,
        const float* __restrict__ scr, const int* rhc, int cg, u64 (*acc)[4])
{
    #pragma unroll
    for (int j = 0; j < RB; j++)
        #pragma unroll
        for (int u = 0; u < 4; u++) {
            u64 part = *(const u64*)(scr + j * 128 + 32 * u + cg * 2);
            float* dst = s_res + (rhc[j] >> 1) + cg * 2 + 32 * u;
            *(u64*)dst = f2add(*(const u64*)dst, f2add(acc[j][u], part));
        }
}

// ---------------- fused 4-iteration kernel, 8 nodes per CTA, 512 threads ----------------
__global__ void __launch_bounds__(NT, 1)
cg_kernel(const float* __restrict__ f0, const float* __restrict__ f1,
          const float* __restrict__ f2, const float* __restrict__ U,
          const float* __restrict__ gamma, const float* __restrict__ Win,
          const float* __restrict__ Wout, float* __restrict__ out)
{
    extern __shared__ float sm[];
    float* s_res = sm + OFF_RES;
    float* s_h   = sm + OFF_H;
    float* s_hc  = sm + OFF_HC;
    float* s_U   = sm + OFF_U;
    float* s_g   = sm + OFF_G;

    const int tid = threadIdx.x;
    const int n0  = blockIdx.x * BN;

    // ----- lin_in task mapping (as round 10, validated) -----
    int li_roff[10];
    int li_pg, li_ks, li_l;
    if (tid < 256) {            // l=2: 4 bmg x 32 pg x 2 ks
        li_l = 2; li_pg = tid & 31;
        int bmg = (tid >> 5) & 3; li_ks = tid >> 7;
        #pragma unroll
        for (int j = 0; j < 10; j++) {
            int idx = bmg * 10 + j;
            int b = idx / 5, q = idx - b * 5;
            li_roff[j] = (b * 9 + 4 + q) * 128;
        }
    } else if (tid < 448) {     // l=1: 3 bmg x 32 pg x 2 ks
        li_l = 1; int t = tid - 256; li_pg = t & 31;
        int g = t >> 5; int bmg = g % 3; li_ks = g / 3;
        #pragma unroll
        for (int j = 0; j < 8; j++) {
            int idx = bmg * 8 + j;
            int b = idx / 3, q = idx - b * 3;
            li_roff[j] = (b * 9 + 1 + q) * 128;
        }
        li_roff[8] = li_roff[9] = 0;
    } else {                    // l=0: 1 x 32 pg x 2 ks
        li_l = 0; int t = tid - 448; li_pg = t & 31; li_ks = t >> 5;
        #pragma unroll
        for (int j = 0; j < 8; j++) li_roff[j] = j * 9 * 128;
        li_roff[8] = li_roff[9] = 0;
    }

    // ----- lin_out task mapping: 512 tasks, scratch rows [l0:0-7 | l1:8-31 | l2:32-71] -----
    int lo_roff[5];
    int lo_cg, lo_ps, lo_l;
    float* lo_scr;
    if (tid < 256) {            // l=2: 8 bmg(5 rows = node bmg) x 16 cg x 2 ps
        lo_l = 2; lo_cg = tid & 15;
        int bmg = (tid >> 4) & 7; lo_ps = tid >> 7;
        lo_scr = s_h + (32 + bmg * 5) * 128;
        #pragma unroll
        for (int j = 0; j < 5; j++) lo_roff[j] = (bmg * 9 + 4 + j) * 256;
    } else if (tid < 448) {     // l=1: 6 bmg(4 rows) x 16 cg x 2 ps
        lo_l = 1; int t = tid - 256; lo_cg = t & 15;
        int g = t >> 4; int bmg = g % 6; lo_ps = g / 6;
        lo_scr = s_h + (8 + bmg * 4) * 128;
        #pragma unroll
        for (int j = 0; j < 4; j++) {
            int idx = bmg * 4 + j;
            int b = idx / 3, q = idx - b * 3;
            lo_roff[j] = (b * 9 + 1 + q) * 256;
        }
        lo_roff[4] = 0;
    } else {                    // l=0: 2 bmg(4 rows) x 16 cg x 2 ps
        lo_l = 0; int t = tid - 448; lo_cg = t & 15;
        int g = t >> 4; int bmg = g & 1; lo_ps = g >> 1;
        lo_scr = s_h + (bmg * 4) * 128;
        #pragma unroll
        for (int j = 0; j < 4; j++) lo_roff[j] = (bmg * 4 + j) * 9 * 256;
        lo_roff[4] = 0;
    }

    // --- load features: s_res[b][m][k], m packed [f0 | f1(3) | f2(5)] ---
    {
        float4* dst = (float4*)s_res;
        for (int idx = tid; idx < BN * 9 * 32; idx += NT) {
            int b   = idx / 288;
            int rem = idx - b * 288;
            int m   = rem >> 5;
            int q   = rem & 31;
            int n   = n0 + b;
            const float* src;
            if (m == 0)      src = f0 + (size_t)n * 128;
            else if (m < 4)  src = f1 + (size_t)n * 384 + (m - 1) * 128;
            else             src = f2 + (size_t)n * 640 + (m - 4) * 128;
            dst[idx] = ((const float4*)src)[q];
        }
    }
    // --- symmetrize U into scalar pair layout s_U[pair][c] ---
    for (int tt = tid; tt < 45 * 9; tt += NT) {
        int pair = tt / 9, c = tt - pair * 9;
        int a = 0, rem = pair;
        while (rem > 8 - a) { rem -= 9 - a; a++; }
        int bb = a + rem;
        float u = U[(a * 9 + bb) * 9 + c];
        if (a != bb) u += U[(bb * 9 + a) * 9 + c];
        s_U[pair * 9 + c] = u;
    }
    for (int tt = tid; tt < NI * 3 * KC; tt += NT) s_g[tt] = gamma[tt];
    __syncthreads();

    u64 acc[10][4];

    #pragma unroll 1
    for (int it = 0; it < NI; it++) {
        // ---------- EquivariantRMSNorm -> natural h[b][m][k] ----------
        for (int idx = tid; idx < BN * KC; idx += NT) {
            int b = idx >> 7, k = idx & 127;
            const float* r = s_res + b * 1152 + k;
            float x0 = r[0];
            float x1 = r[128], x2 = r[256],  x3 = r[384];
            float x4 = r[512], x5 = r[640],  x6 = r[768], x7 = r[896], x8 = r[1024];
            float i0 = rsqrtf(x0 * x0 + EPSV);
            float i1 = rsqrtf((x1*x1 + x2*x2 + x3*x3) * (1.0f/3.0f) + EPSV);
            float i2 = rsqrtf((x4*x4 + x5*x5 + x6*x6 + x7*x7 + x8*x8) * 0.2f + EPSV);
            float g0 = s_g[(it * 3 + 0) * 128 + k];
            float g1 = s_g[(it * 3 + 1) * 128 + k];
            float g2 = s_g[(it * 3 + 2) * 128 + k];
            float* h = s_h + b * 1152 + k;
            h[0]    = x0 * i0 * g0;
            h[128]  = x1 * i1 * g1;
            h[256]  = x2 * i1 * g1;
            h[384]  = x3 * i1 * g1;
            h[512]  = x4 * i2 * g2;
            h[640]  = x5 * i2 * g2;
            h[768]  = x6 * i2 * g2;
            h[896]  = x7 * i2 * g2;
            h[1024] = x8 * i2 * g2;
        }
        __syncthreads();

        // ---------- linear_in (K -> 2K): register-tiled, k-halves ----------
        {
            const float* Wl = Win + (size_t)(it * 3 + li_l) * KC * PC;
            if (tid < 256)       li_body<10>(Wl, s_h, s_hc, li_roff, li_pg, li_ks, acc);
            else if (tid < 448)  li_body<8>(Wl, s_h, s_hc, li_roff, li_pg, li_ks, acc);
            else                 li_body<8>(Wl, s_h, s_hc, li_roff, li_pg, li_ks, acc);
        }
        __syncthreads();
        if (li_ks == 0) {
            if (tid < 256)       li_fin<10>(s_hc, li_roff, li_pg, acc);
            else if (tid < 448)  li_fin<8>(s_hc, li_roff, li_pg, acc);
            else                 li_fin<8>(s_hc, li_roff, li_pg, acc);
        }
        __syncthreads();

        // ---------- CG tensor product, register-preloaded, in-place on s_hc ----------
        {
            const int p2 = tid & 127;
            const int bq = (tid >> 7) * 2;
            float* base0 = s_hc + bq * 2304 + 2 * p2;
            float* base1 = base0 + 2304;
            u64 v0[9], v1[9];
            #pragma unroll
            for (int a = 0; a < 9; a++) {
                v0[a] = *(const u64*)(base0 + a * 256);
                v1[a] = *(const u64*)(base1 + a * 256);
            }
            u64 acc0[9], acc1[9];
            #pragma unroll
            for (int c = 0; c < 9; c++) { acc0[c] = 0ull; acc1[c] = 0ull; }
            int pair = 0;
            for (int a = 0; a < 9; a++) {
                for (int bb = a; bb < 9; bb++) {
                    u64 pr0 = f2mul(v0[a], v0[bb]);
                    u64 pr1 = f2mul(v1[a], v1[bb]);
                    const float* u = s_U + pair * 9;
                    #pragma unroll
                    for (int c = 0; c < 9; c++) {
                        float us = u[c];
                        u64 uc = fpack(us, us);
                        acc0[c] = f2fma(pr0, uc, acc0[c]);
                        acc1[c] = f2fma(pr1, uc, acc1[c]);
                    }
                    pair++;
                }
            }
            #pragma unroll
            for (int c = 0; c < 9; c++) {
                *(u64*)(base0 + c * 256) = acc0[c];
                *(u64*)(base1 + c * 256) = acc1[c];
            }
        }
        __syncthreads();

        // ---------- linear_out (2K -> K) + skip: register-tiled, p-halves, 512 tasks ----------
        {
            const float* Wl = Wout + (size_t)(it * 3 + lo_l) * PC * KC;
            if (tid < 256)       lo_body<5>(Wl, s_hc, lo_scr, lo_roff, lo_cg, lo_ps, acc);
            else if (tid < 448)  lo_body<4>(Wl, s_hc, lo_scr, lo_roff, lo_cg, lo_ps, acc);
            else                 lo_body<4>(Wl, s_hc, lo_scr, lo_roff, lo_cg, lo_ps, acc);
        }
        __syncthreads();
        if (lo_ps == 0) {
            if (tid < 256)       lo_fin<5>(s_res, lo_scr, lo_roff, lo_cg, acc);
            else if (tid < 448)  lo_fin<4>(s_res, lo_scr, lo_roff, lo_cg, acc);
            else                 lo_fin<4>(s_res, lo_scr, lo_roff, lo_cg, acc);
        }
        __syncthreads();
    }

    // --- write out [N][9][128] ---
    {
        float4* o = (float4*)(out + (size_t)n0 * 1152);
        const float4* s = (const float4*)s_res;
        for (int idx = tid; idx < BN * 9 * 32; idx += NT) o[idx] = s[idx];
    }
}

extern "C" void kernel_launch(void* const* d_in, const int* in_sizes, int n_in,
                              void* d_out, int out_size)
{
    const float* f0 = (const float*)d_in[0];
    const float* f1 = (const float*)d_in[1];
    const float* f2 = (const float*)d_in[2];
    const float* U  = (const float*)d_in[3];
    const float* g  = (const float*)d_in[4];
    const float* Wi = (const float*)d_in[5];
    const float* Wo = (const float*)d_in[6];
    float* out = (float*)d_out;

    const int smem_bytes = SMEM_FLOATS * (int)sizeof(float);
    cudaFuncSetAttribute(cg_kernel, cudaFuncAttributeMaxDynamicSharedMemorySize, smem_bytes);
    cg_kernel<<<NN / BN, NT, smem_bytes>>>(f0, f1, f2, U, g, Wi, Wo, out);
}